// round 5
// baseline (speedup 1.0000x reference)
#include <cuda_runtime.h>

#define BN    8
#define NPIX  (224*224)   // 50176
#define SS    196
#define EE    768
#define NBLK  49          // blocks per image in k_main
#define TPB   128         // threads per block in k_main
#define PXT   8           // pixels per thread  (49*128*8 = 50176 exactly)

// ---- per-block partial sums (written unconditionally -> no init kernel) ----
__device__ float g_psum [BN*NBLK*SS];     // sum exp
__device__ float g_pp0  [BN*NBLK*SS];     // sum e*c0
__device__ float g_pp1  [BN*NBLK*SS];
__device__ float g_pp2  [BN*NBLK*SS];
__device__ int   g_pcnt [BN*NBLK*SS];     // pixel count

// Fused pass: 196-way argmax per pixel + exp(score), accumulated in shared
// per-segment slots; each block flushes to its private partial slice.
// Softmax shift-invariance => no max subtraction needed (scores are O(10)).
__global__ __launch_bounds__(TPB) void k_main(
        const float* __restrict__ img,
        const float* __restrict__ Wseg,
        const float* __restrict__ bseg,
        const float* __restrict__ wq){
    __shared__ float4 sW[SS];
    __shared__ float  ssum[SS], sp0[SS], sp1[SS], sp2[SS];
    __shared__ int    scnt[SS];
    int t = threadIdx.x;
    for (int i = t; i < SS; i += TPB){
        sW[i]  = make_float4(Wseg[3*i], Wseg[3*i+1], Wseg[3*i+2], bseg[i]);
        ssum[i]=0.f; sp0[i]=0.f; sp1[i]=0.f; sp2[i]=0.f; scnt[i]=0;
    }
    __syncthreads();

    int b = blockIdx.y;
    const float* im = img + (size_t)b*3*NPIX;
    int n = (blockIdx.x*TPB + t)*PXT;          // 8 consecutive pixels

    // load 8 pixels x 3 channels as float4 pairs
    float c0[PXT], c1[PXT], c2[PXT];
    {
        float4 u0 = *(const float4*)(im + n);
        float4 u1 = *(const float4*)(im + n + 4);
        float4 v0 = *(const float4*)(im + NPIX + n);
        float4 v1 = *(const float4*)(im + NPIX + n + 4);
        float4 w0 = *(const float4*)(im + 2*NPIX + n);
        float4 w1 = *(const float4*)(im + 2*NPIX + n + 4);
        c0[0]=u0.x; c0[1]=u0.y; c0[2]=u0.z; c0[3]=u0.w;
        c0[4]=u1.x; c0[5]=u1.y; c0[6]=u1.z; c0[7]=u1.w;
        c1[0]=v0.x; c1[1]=v0.y; c1[2]=v0.z; c1[3]=v0.w;
        c1[4]=v1.x; c1[5]=v1.y; c1[6]=v1.z; c1[7]=v1.w;
        c2[0]=w0.x; c2[1]=w0.y; c2[2]=w0.z; c2[3]=w0.w;
        c2[4]=w1.x; c2[5]=w1.y; c2[6]=w1.z; c2[7]=w1.w;
    }

    float best[PXT]; int bi[PXT];
    #pragma unroll
    for (int p = 0; p < PXT; p++){ best[p] = -3.4e38f; bi[p] = 0; }

    #pragma unroll 4
    for (int s = 0; s < SS; s++){
        float4 w = sW[s];           // one LDS.128 amortized over 8 pixels
        #pragma unroll
        for (int p = 0; p < PXT; p++){
            float l = fmaf(c0[p], w.x, fmaf(c1[p], w.y, fmaf(c2[p], w.z, w.w)));
            bool gt = (l > best[p]);          // strict > keeps lowest-index ties
            best[p] = gt ? l : best[p];
            bi[p]   = gt ? s : bi[p];
        }
    }

    float q0 = wq[0], q1 = wq[1], q2 = wq[2];
    #pragma unroll
    for (int p = 0; p < PXT; p++){
        float score = fmaf(c0[p], q0, fmaf(c1[p], q1, c2[p]*q2));
        float e = __expf(score);
        int s = bi[p];
        atomicAdd(&ssum[s], e);
        atomicAdd(&sp0[s], e*c0[p]);
        atomicAdd(&sp1[s], e*c1[p]);
        atomicAdd(&sp2[s], e*c2[p]);
        atomicAdd(&scnt[s], 1);
    }
    __syncthreads();

    // flush partials (unconditional, so no global pre-zero required)
    int base = (b*NBLK + blockIdx.x)*SS;
    for (int i = t; i < SS; i += TPB){
        g_psum[base+i] = ssum[i];
        g_pp0 [base+i] = sp0[i];
        g_pp1 [base+i] = sp1[i];
        g_pp2 [base+i] = sp2[i];
        g_pcnt[base+i] = scnt[i];
    }
}

// Reduce the 49 per-block partials per (b,s), normalize (denominator includes
// the (NPIX-count) exp(0)=1 background terms), project to E=768.
__global__ void k_out(const float* __restrict__ Wout,
                      const float* __restrict__ bout,
                      float* __restrict__ out){
    int bs = blockIdx.x;                 // b*SS + s
    int b = bs / SS, s = bs - b*SS;
    __shared__ float asum, a0, a1, a2;
    __shared__ int   acnt;
    if (threadIdx.x == 0){ asum=0.f; a0=0.f; a1=0.f; a2=0.f; acnt=0; }
    __syncthreads();

    for (int i = threadIdx.x; i < NBLK; i += blockDim.x){
        int idx = (b*NBLK + i)*SS + s;
        atomicAdd(&asum, g_psum[idx]);
        atomicAdd(&a0,   g_pp0[idx]);
        atomicAdd(&a1,   g_pp1[idx]);
        atomicAdd(&a2,   g_pp2[idx]);
        atomicAdd(&acnt, g_pcnt[idx]);
    }
    __syncthreads();

    int cnt = acnt;
    float p0 = 0.f, p1 = 0.f, p2 = 0.f;
    if (cnt > 0){
        float D   = asum + (float)(NPIX - cnt);
        float inv = 1.0f / D;
        p0 = a0 * inv; p1 = a1 * inv; p2 = a2 * inv;
    }
    float* o = out + (size_t)bs * EE;
    for (int e = threadIdx.x; e < EE; e += blockDim.x){
        float v = 0.f;
        if (cnt > 0)
            v = fmaf(p0, Wout[3*e+0], fmaf(p1, Wout[3*e+1], fmaf(p2, Wout[3*e+2], bout[e])));
        o[e] = v;
    }
}

extern "C" void kernel_launch(void* const* d_in, const int* in_sizes, int n_in,
                              void* d_out, int out_size) {
    const float* img  = (const float*)d_in[0];   // [8,3,224,224]
    const float* Wseg = (const float*)d_in[1];   // [196,3]
    const float* bseg = (const float*)d_in[2];   // [196]
    const float* wq   = (const float*)d_in[3];   // [3]
    const float* Wout = (const float*)d_in[4];   // [768,3]
    const float* bout = (const float*)d_in[5];   // [768]
    float* out = (float*)d_out;                  // [8,196,768]

    dim3 g(NBLK, BN);                            // 392 blocks
    k_main<<<g, TPB>>>(img, Wseg, bseg, wq);
    k_out<<<BN*SS, 256>>>(Wout, bout, out);
}

// round 6
// speedup vs baseline: 1.3687x; 1.3687x over previous
#include <cuda_runtime.h>

#define BN    8
#define NPIX  (224*224)   // 50176
#define SS    196
#define EE    768
#define NBLK  49          // blocks per image in k_main
#define TPB   256         // threads per block in k_main
#define PXT   4           // pixels per thread  (49*256*4 = 50176 exactly)
#define ROWS_PER_BLK 4    // (b,s) rows per k_out block; 1568/4 = 392 blocks

// ---- per-block partial sums (written unconditionally -> no init kernel) ----
__device__ float g_psum [BN*NBLK*SS];     // sum exp
__device__ float g_pp0  [BN*NBLK*SS];     // sum e*c0
__device__ float g_pp1  [BN*NBLK*SS];
__device__ float g_pp2  [BN*NBLK*SS];
__device__ int   g_pcnt [BN*NBLK*SS];     // pixel count

// Fused pass: 196-way argmax per pixel + exp(score), accumulated in shared
// per-segment slots; each block flushes its private partial slice.
// Softmax shift-invariance => no max subtraction needed (scores are O(10)).
__global__ __launch_bounds__(TPB) void k_main(
        const float* __restrict__ img,
        const float* __restrict__ Wseg,
        const float* __restrict__ bseg,
        const float* __restrict__ wq){
    __shared__ float4 sW[SS];
    __shared__ float  ssum[SS], sp0[SS], sp1[SS], sp2[SS];
    __shared__ int    scnt[SS];
    int t = threadIdx.x;
    if (t < SS){
        sW[t]  = make_float4(Wseg[3*t], Wseg[3*t+1], Wseg[3*t+2], bseg[t]);
        ssum[t]=0.f; sp0[t]=0.f; sp1[t]=0.f; sp2[t]=0.f; scnt[t]=0;
    }
    __syncthreads();

    int b = blockIdx.y;
    const float* im = img + (size_t)b*3*NPIX;
    int n = (blockIdx.x*TPB + t)*PXT;          // 4 consecutive pixels

    float c0[PXT], c1[PXT], c2[PXT];
    {
        float4 u = *(const float4*)(im + n);
        float4 v = *(const float4*)(im + NPIX + n);
        float4 w = *(const float4*)(im + 2*NPIX + n);
        c0[0]=u.x; c0[1]=u.y; c0[2]=u.z; c0[3]=u.w;
        c1[0]=v.x; c1[1]=v.y; c1[2]=v.z; c1[3]=v.w;
        c2[0]=w.x; c2[1]=w.y; c2[2]=w.z; c2[3]=w.w;
    }

    float best[PXT]; int bi[PXT];
    #pragma unroll
    for (int p = 0; p < PXT; p++){ best[p] = -3.4e38f; bi[p] = 0; }

    #pragma unroll 4
    for (int s = 0; s < SS; s++){
        float4 w = sW[s];           // one broadcast LDS.128 amortized over 4 px
        #pragma unroll
        for (int p = 0; p < PXT; p++){
            float l = fmaf(c0[p], w.x, fmaf(c1[p], w.y, fmaf(c2[p], w.z, w.w)));
            bool gt = (l > best[p]);          // strict > keeps lowest-index ties
            best[p] = gt ? l : best[p];
            bi[p]   = gt ? s : bi[p];
        }
    }

    float q0 = wq[0], q1 = wq[1], q2 = wq[2];
    #pragma unroll
    for (int p = 0; p < PXT; p++){
        float score = fmaf(c0[p], q0, fmaf(c1[p], q1, c2[p]*q2));
        float e = __expf(score);
        int s = bi[p];
        atomicAdd(&ssum[s], e);
        atomicAdd(&sp0[s], e*c0[p]);
        atomicAdd(&sp1[s], e*c1[p]);
        atomicAdd(&sp2[s], e*c2[p]);
        atomicAdd(&scnt[s], 1);
    }
    __syncthreads();

    // flush partials (unconditional, so no global pre-zero required)
    int base = (b*NBLK + blockIdx.x)*SS;
    if (t < SS){
        g_psum[base+t] = ssum[t];
        g_pp0 [base+t] = sp0[t];
        g_pp1 [base+t] = sp1[t];
        g_pp2 [base+t] = sp2[t];
        g_pcnt[base+t] = scnt[t];
    }
}

// Fused reduce + project: each block owns ROWS_PER_BLK (b,s) rows.
// One warp per row reduces the 49 partials (shfl tree), then the block
// projects its rows through Wout (staged in smem) with coalesced stores.
__global__ __launch_bounds__(128) void k_out(
        const float* __restrict__ Wout,
        const float* __restrict__ bout,
        float* __restrict__ out){
    __shared__ float4 sWo[EE];          // (w0,w1,w2,bias) per e  -> 12 KB
    __shared__ float4 srow[ROWS_PER_BLK]; // (p0,p1,p2,valid)
    int t = threadIdx.x, lane = t & 31, w = t >> 5;

    for (int e = t; e < EE; e += 128)
        sWo[e] = make_float4(Wout[3*e], Wout[3*e+1], Wout[3*e+2], bout[e]);

    // warp w reduces row bs = blockIdx.x*ROWS_PER_BLK + w
    int bs = blockIdx.x*ROWS_PER_BLK + w;
    int b = bs / SS, s = bs - b*SS;
    int base = b*NBLK*SS + s;
    float vsum = 0.f, v0 = 0.f, v1 = 0.f, v2 = 0.f;
    int   vcnt = 0;
    {
        int i = lane;
        int idx = base + i*SS;
        vsum = g_psum[idx]; v0 = g_pp0[idx]; v1 = g_pp1[idx]; v2 = g_pp2[idx];
        vcnt = g_pcnt[idx];
        if (i + 32 < NBLK){
            int idx2 = base + (i+32)*SS;
            vsum += g_psum[idx2]; v0 += g_pp0[idx2]; v1 += g_pp1[idx2]; v2 += g_pp2[idx2];
            vcnt += g_pcnt[idx2];
        }
    }
    #pragma unroll
    for (int off = 16; off; off >>= 1){
        vsum += __shfl_down_sync(0xffffffffu, vsum, off);
        v0   += __shfl_down_sync(0xffffffffu, v0,   off);
        v1   += __shfl_down_sync(0xffffffffu, v1,   off);
        v2   += __shfl_down_sync(0xffffffffu, v2,   off);
        vcnt += __shfl_down_sync(0xffffffffu, vcnt, off);
    }
    if (lane == 0){
        float4 r = make_float4(0.f, 0.f, 0.f, 0.f);
        if (vcnt > 0){
            float D   = vsum + (float)(NPIX - vcnt);   // background exp(0)=1 terms
            float inv = 1.0f / D;
            r = make_float4(v0*inv, v1*inv, v2*inv, 1.0f);
        }
        srow[w] = r;
    }
    __syncthreads();

    // projection: rows r, coalesced over e
    #pragma unroll
    for (int r = 0; r < ROWS_PER_BLK; r++){
        float4 p = srow[r];
        float* o = out + (size_t)(blockIdx.x*ROWS_PER_BLK + r)*EE;
        #pragma unroll
        for (int e = t; e < EE; e += 128){
            float4 wv = sWo[e];
            // valid=0 => p = 0 and bias suppressed => exact 0
            o[e] = fmaf(p.x, wv.x, fmaf(p.y, wv.y, fmaf(p.z, wv.z, p.w*wv.w)));
        }
    }
}

extern "C" void kernel_launch(void* const* d_in, const int* in_sizes, int n_in,
                              void* d_out, int out_size) {
    const float* img  = (const float*)d_in[0];   // [8,3,224,224]
    const float* Wseg = (const float*)d_in[1];   // [196,3]
    const float* bseg = (const float*)d_in[2];   // [196]
    const float* wq   = (const float*)d_in[3];   // [3]
    const float* Wout = (const float*)d_in[4];   // [768,3]
    const float* bout = (const float*)d_in[5];   // [768]
    float* out = (float*)d_out;                  // [8,196,768]

    dim3 g(NBLK, BN);                            // 392 blocks, 256 thr
    k_main<<<g, TPB>>>(img, Wseg, bseg, wq);
    k_out<<<(BN*SS)/ROWS_PER_BLK, 128>>>(Wout, bout, out);  // 392 blocks
}

// round 7
// speedup vs baseline: 1.4678x; 1.0723x over previous
#include <cuda_runtime.h>

#define BN    8
#define NPIX  (224*224)   // 50176
#define SS    196
#define EE    768
#define NBLK  98          // blocks per image in k_main
#define TPB   256         // threads per block in k_main
#define PXT   2           // pixels per thread  (98*256*2 = 50176 exactly)
#define ROWS_PER_BLK 16   // (b,s) rows per k_out block; 1568/16 = 98 blocks

// ---- per-block partial sums (written unconditionally -> no init kernel) ----
__device__ float g_psum [BN*NBLK*SS];     // sum exp
__device__ float g_pp0  [BN*NBLK*SS];     // sum e*c0
__device__ float g_pp1  [BN*NBLK*SS];
__device__ float g_pp2  [BN*NBLK*SS];
__device__ int   g_pcnt [BN*NBLK*SS];     // pixel count

// Fused pass: 196-way argmax per pixel + exp(score), accumulated in shared
// per-segment slots; each block flushes its private partial slice.
// Softmax shift-invariance => no max subtraction needed (scores are O(10)).
__global__ __launch_bounds__(TPB) void k_main(
        const float* __restrict__ img,
        const float* __restrict__ Wseg,
        const float* __restrict__ bseg,
        const float* __restrict__ wq){
    __shared__ float4 sW[SS];
    __shared__ float  ssum[SS], sp0[SS], sp1[SS], sp2[SS];
    __shared__ int    scnt[SS];
    int t = threadIdx.x;
    if (t < SS){
        sW[t]  = make_float4(Wseg[3*t], Wseg[3*t+1], Wseg[3*t+2], bseg[t]);
        ssum[t]=0.f; sp0[t]=0.f; sp1[t]=0.f; sp2[t]=0.f; scnt[t]=0;
    }
    __syncthreads();

    int b = blockIdx.y;
    const float* im = img + (size_t)b*3*NPIX;
    int n = (blockIdx.x*TPB + t)*PXT;          // 2 consecutive pixels

    float c0[PXT], c1[PXT], c2[PXT];
    {
        float2 u = *(const float2*)(im + n);
        float2 v = *(const float2*)(im + NPIX + n);
        float2 w = *(const float2*)(im + 2*NPIX + n);
        c0[0]=u.x; c0[1]=u.y;
        c1[0]=v.x; c1[1]=v.y;
        c2[0]=w.x; c2[1]=w.y;
    }

    float best[PXT]; int bi[PXT];
    #pragma unroll
    for (int p = 0; p < PXT; p++){ best[p] = -3.4e38f; bi[p] = 0; }

    #pragma unroll 7
    for (int s = 0; s < SS; s++){
        float4 w = sW[s];           // one broadcast LDS.128 per 2 px
        #pragma unroll
        for (int p = 0; p < PXT; p++){
            float l = fmaf(c0[p], w.x, fmaf(c1[p], w.y, fmaf(c2[p], w.z, w.w)));
            bool gt = (l > best[p]);          // strict > keeps lowest-index ties
            best[p] = gt ? l : best[p];
            bi[p]   = gt ? s : bi[p];
        }
    }

    float q0 = wq[0], q1 = wq[1], q2 = wq[2];
    #pragma unroll
    for (int p = 0; p < PXT; p++){
        float score = fmaf(c0[p], q0, fmaf(c1[p], q1, c2[p]*q2));
        float e = __expf(score);
        int s = bi[p];
        atomicAdd(&ssum[s], e);
        atomicAdd(&sp0[s], e*c0[p]);
        atomicAdd(&sp1[s], e*c1[p]);
        atomicAdd(&sp2[s], e*c2[p]);
        atomicAdd(&scnt[s], 1);
    }
    __syncthreads();

    // flush partials (unconditional, so no global pre-zero required)
    int base = (b*NBLK + blockIdx.x)*SS;
    if (t < SS){
        g_psum[base+t] = ssum[t];
        g_pp0 [base+t] = sp0[t];
        g_pp1 [base+t] = sp1[t];
        g_pp2 [base+t] = sp2[t];
        g_pcnt[base+t] = scnt[t];
    }
}

// Fused reduce + project: 98 blocks x 256 threads; each block owns 16 rows.
// Wout staged once per block (amortized over 16 rows); one warp reduces 2 rows
// via lane-parallel partial loads + shfl tree; stores fully coalesced.
__global__ __launch_bounds__(256) void k_out(
        const float* __restrict__ Wout,
        const float* __restrict__ bout,
        float* __restrict__ out){
    __shared__ float4 sWo[EE];              // (w0,w1,w2,bias) -> 12 KB
    __shared__ float4 srow[ROWS_PER_BLK];   // (p0,p1,p2,biasScale)
    int t = threadIdx.x, lane = t & 31, w = t >> 5;

    for (int e = t; e < EE; e += 256)
        sWo[e] = make_float4(Wout[3*e], Wout[3*e+1], Wout[3*e+2], bout[e]);

    // 8 warps x 2 rows each
    #pragma unroll
    for (int rr = 0; rr < 2; rr++){
        int r  = w*2 + rr;
        int bs = blockIdx.x*ROWS_PER_BLK + r;
        int b = bs / SS, s = bs - b*SS;
        int base = b*NBLK*SS + s;
        float vsum = 0.f, v0 = 0.f, v1 = 0.f, v2 = 0.f;
        int   vcnt = 0;
        #pragma unroll
        for (int i = lane; i < NBLK; i += 32){
            int idx = base + i*SS;
            vsum += g_psum[idx]; v0 += g_pp0[idx];
            v1   += g_pp1[idx];  v2 += g_pp2[idx];
            vcnt += g_pcnt[idx];
        }
        #pragma unroll
        for (int off = 16; off; off >>= 1){
            vsum += __shfl_down_sync(0xffffffffu, vsum, off);
            v0   += __shfl_down_sync(0xffffffffu, v0,   off);
            v1   += __shfl_down_sync(0xffffffffu, v1,   off);
            v2   += __shfl_down_sync(0xffffffffu, v2,   off);
            vcnt += __shfl_down_sync(0xffffffffu, vcnt, off);
        }
        if (lane == 0){
            float4 rv = make_float4(0.f, 0.f, 0.f, 0.f);
            if (vcnt > 0){
                float D   = vsum + (float)(NPIX - vcnt);  // background exp(0)=1
                float inv = 1.0f / D;
                rv = make_float4(v0*inv, v1*inv, v2*inv, 1.0f);
            }
            srow[r] = rv;
        }
    }
    __syncthreads();

    // projection: 16 rows, coalesced over e
    #pragma unroll
    for (int r = 0; r < ROWS_PER_BLK; r++){
        float4 p = srow[r];
        float* o = out + (size_t)(blockIdx.x*ROWS_PER_BLK + r)*EE;
        #pragma unroll
        for (int e = t; e < EE; e += 256){
            float4 wv = sWo[e];
            // invalid row => p = (0,0,0,0) -> exact 0 (bias suppressed)
            o[e] = fmaf(p.x, wv.x, fmaf(p.y, wv.y, fmaf(p.z, wv.z, p.w*wv.w)));
        }
    }
}

extern "C" void kernel_launch(void* const* d_in, const int* in_sizes, int n_in,
                              void* d_out, int out_size) {
    const float* img  = (const float*)d_in[0];   // [8,3,224,224]
    const float* Wseg = (const float*)d_in[1];   // [196,3]
    const float* bseg = (const float*)d_in[2];   // [196]
    const float* wq   = (const float*)d_in[3];   // [3]
    const float* Wout = (const float*)d_in[4];   // [768,3]
    const float* bout = (const float*)d_in[5];   // [768]
    float* out = (float*)d_out;                  // [8,196,768]

    dim3 g(NBLK, BN);                            // 784 blocks, 256 thr
    k_main<<<g, TPB>>>(img, Wseg, bseg, wq);
    k_out<<<(BN*SS)/ROWS_PER_BLK, 256>>>(Wout, bout, out);  // 98 blocks
}